// round 1
// baseline (speedup 1.0000x reference)
#include <cuda_runtime.h>
#include <math.h>

#define NB 8192
#define NT 21
#define NF 3
#define NU 512
#define NZ 2048   // 4*U

// ---------------- persistent scratch (device globals; no allocations) -------
__device__ float g_h  [NB * NU];   // LSTM hidden state
__device__ float g_c  [NB * NU];   // LSTM cell state
__device__ float g_hr0[NB * NU];   // RNN state ping
__device__ float g_hr1[NB * NU];   // RNN state pong
__device__ float g_oc [NB * NU];   // o_comp (pre-gather)
__device__ float g_tc [NB * NU];   // tanh(c_new)
__device__ int   g_oidx[NT * NB];
__device__ unsigned char g_m[NT * NB];
__device__ float g_weff[NU];
__device__ float g_beff;

__device__ __forceinline__ float sigf(float z) { return 1.0f / (1.0f + expf(-z)); }

// ---------------- init: zero states (must run every replay) -----------------
__global__ void k_init() {
    int i = blockIdx.x * blockDim.x + threadIdx.x;
    g_h[i] = 0.f; g_c[i] = 0.f; g_hr0[i] = 0.f; g_hr1[i] = 0.f;
}

// ---------------- mask forcing + cross-batch cummax gather index ------------
// One block per timestep t; 1024 threads, 8 elements each.
__global__ void k_oidx(const int* __restrict__ learn) {
    int t = blockIdx.x;
    int tid = threadIdx.x;
    __shared__ int s_any, s_first;
    __shared__ int s_scan[1024];
    if (tid == 0) { s_any = 0; s_first = 0x7fffffff; }
    __syncthreads();

    int base = tid * 8;
    int m[8]; int la = 0;
#pragma unroll
    for (int j = 0; j < 8; j++) { m[j] = (learn[t * NB + base + j] == 1) ? 1 : 0; la |= m[j]; }
    if (la) atomicOr(&s_any, 1);
    __syncthreads();
    if (tid == 0 && !s_any) m[0] = 1;   // force row 0 to learn when none do

    int lf = 0x7fffffff;
#pragma unroll
    for (int j = 0; j < 8; j++) if (m[j] && lf == 0x7fffffff) lf = base + j;
    if (lf != 0x7fffffff) atomicMin(&s_first, lf);

    // local cummax of (m ? index : -1)
    int run = -1; int lv[8];
#pragma unroll
    for (int j = 0; j < 8; j++) { if (m[j]) run = base + j; lv[j] = run; }
    s_scan[tid] = run;
    __syncthreads();
    // Hillis-Steele inclusive max scan over 1024 thread maxima
    for (int off = 1; off < 1024; off <<= 1) {
        int other = (tid >= off) ? s_scan[tid - off] : -1;
        __syncthreads();
        if (other > s_scan[tid]) s_scan[tid] = other;
        __syncthreads();
    }
    int prefix = (tid > 0) ? s_scan[tid - 1] : -1;
    int first = s_first;
#pragma unroll
    for (int j = 0; j < 8; j++) {
        int v = (lv[j] >= 0) ? lv[j] : prefix;
        g_oidx[t * NB + base + j] = (v < 0) ? first : v;
        g_m[t * NB + base + j] = (unsigned char)m[j];
    }
}

// ---------------- LSTM gate GEMM + epilogue ---------------------------------
// z[:, g*512+u] = x_t@kernel + h@recurrent_kernel + bias, all 4 gates per tile.
// Block: 256 thr; tile M=64 rows x 32 u-cols (=> 128 z-cols). Micro 4x(4g)x2.
__global__ void __launch_bounds__(256) k_lstm(
    const float* __restrict__ x, const float* __restrict__ Wk,
    const float* __restrict__ Rk, const float* __restrict__ bias, int t)
{
    const int u0 = blockIdx.x * 32;
    const int m0 = blockIdx.y * 64;
    const int l  = threadIdx.x;
    const int tx = l & 15, ty = l >> 4;

    __shared__ float As[16][65];    // [k][row], padded
    __shared__ float Bs[16][128];   // [k][gate*32+uu]
    __shared__ float xs[64][4];
    __shared__ float ks[3][128];
    __shared__ float bs[128];

    float acc[4][4][2];
#pragma unroll
    for (int i = 0; i < 4; i++)
#pragma unroll
        for (int g = 0; g < 4; g++) { acc[i][g][0] = 0.f; acc[i][g][1] = 0.f; }

    // preload x tile, input-kernel columns, bias (constant over K loop)
    for (int idx = l; idx < 192; idx += 256) {
        int r = idx / 3, f = idx - r * 3;
        xs[r][f] = x[(size_t)(m0 + r) * (NT * NF) + t * NF + f];
    }
    for (int idx = l; idx < 384; idx += 256) {
        int kk = idx >> 7, cc = idx & 127;
        int gate = cc >> 5, uu = cc & 31;
        ks[kk][cc] = Wk[kk * NZ + gate * NU + u0 + uu];
    }
    if (l < 128) { int gate = l >> 5, uu = l & 31; bs[l] = bias[gate * NU + u0 + uu]; }

    const int arow = l >> 2, aq = l & 3;
    const int kk0 = l >> 5, s0 = l & 31;
    const int bgate = s0 >> 3, bu4 = (s0 & 7) * 4;

    for (int k0 = 0; k0 < NU; k0 += 16) {
        float4 av = *(const float4*)&g_h[(size_t)(m0 + arow) * NU + k0 + aq * 4];
        const float* bsrc = Rk + (size_t)(k0 + kk0) * NZ + bgate * NU + u0 + bu4;
        float4 b0 = *(const float4*)bsrc;
        float4 b1 = *(const float4*)(bsrc + 8 * NZ);
        __syncthreads();
        As[aq * 4 + 0][arow] = av.x;
        As[aq * 4 + 1][arow] = av.y;
        As[aq * 4 + 2][arow] = av.z;
        As[aq * 4 + 3][arow] = av.w;
        *(float4*)&Bs[kk0][bgate * 32 + bu4]     = b0;
        *(float4*)&Bs[kk0 + 8][bgate * 32 + bu4] = b1;
        __syncthreads();
#pragma unroll
        for (int kk = 0; kk < 16; kk++) {
            float a0 = As[kk][ty * 4 + 0];
            float a1 = As[kk][ty * 4 + 1];
            float a2 = As[kk][ty * 4 + 2];
            float a3 = As[kk][ty * 4 + 3];
            float2 b[4];
#pragma unroll
            for (int g = 0; g < 4; g++) b[g] = *(const float2*)&Bs[kk][g * 32 + tx * 2];
#pragma unroll
            for (int g = 0; g < 4; g++) {
                acc[0][g][0] = fmaf(a0, b[g].x, acc[0][g][0]);
                acc[0][g][1] = fmaf(a0, b[g].y, acc[0][g][1]);
                acc[1][g][0] = fmaf(a1, b[g].x, acc[1][g][0]);
                acc[1][g][1] = fmaf(a1, b[g].y, acc[1][g][1]);
                acc[2][g][0] = fmaf(a2, b[g].x, acc[2][g][0]);
                acc[2][g][1] = fmaf(a2, b[g].y, acc[2][g][1]);
                acc[3][g][0] = fmaf(a3, b[g].x, acc[3][g][0]);
                acc[3][g][1] = fmaf(a3, b[g].y, acc[3][g][1]);
            }
        }
    }

    // x @ kernel contribution (F=3)
#pragma unroll
    for (int f = 0; f < NF; f++) {
        float a0 = xs[ty * 4 + 0][f];
        float a1 = xs[ty * 4 + 1][f];
        float a2 = xs[ty * 4 + 2][f];
        float a3 = xs[ty * 4 + 3][f];
        float2 b[4];
#pragma unroll
        for (int g = 0; g < 4; g++) b[g] = *(const float2*)&ks[f][g * 32 + tx * 2];
#pragma unroll
        for (int g = 0; g < 4; g++) {
            acc[0][g][0] = fmaf(a0, b[g].x, acc[0][g][0]);
            acc[0][g][1] = fmaf(a0, b[g].y, acc[0][g][1]);
            acc[1][g][0] = fmaf(a1, b[g].x, acc[1][g][0]);
            acc[1][g][1] = fmaf(a1, b[g].y, acc[1][g][1]);
            acc[2][g][0] = fmaf(a2, b[g].x, acc[2][g][0]);
            acc[2][g][1] = fmaf(a2, b[g].y, acc[2][g][1]);
            acc[3][g][0] = fmaf(a3, b[g].x, acc[3][g][0]);
            acc[3][g][1] = fmaf(a3, b[g].y, acc[3][g][1]);
        }
    }

    // epilogue: gates, masked c update, write c / tanh(c) / o_comp
#pragma unroll
    for (int i = 0; i < 4; i++) {
        int row = m0 + ty * 4 + i;
        unsigned char mk = g_m[t * NB + row];
#pragma unroll
        for (int j = 0; j < 2; j++) {
            int uu = tx * 2 + j;
            int u = u0 + uu;
            float zi = acc[i][0][j] + bs[uu];
            float zf = acc[i][1][j] + bs[32 + uu];
            float zg = acc[i][2][j] + bs[64 + uu];
            float zo = acc[i][3][j] + bs[96 + uu];
            float ig = sigf(zi);
            float fg = sigf(zf);
            float gg = tanhf(zg);
            float og = sigf(zo);
            size_t off = (size_t)row * NU + u;
            float c = g_c[off];
            float cn = mk ? fmaf(fg, c, ig * gg) : c;
            g_c[off]  = cn;
            g_tc[off] = tanhf(cn);
            g_oc[off] = og;
        }
    }
}

// ---------------- cross-batch o gather: h = o_comp[oidx] * tanh(c) ----------
__global__ void k_gather(int t) {
    int i = blockIdx.x * blockDim.x + threadIdx.x;   // over NB*NU/4
    int b = i >> 7, q = i & 127;
    int src = g_oidx[t * NB + b];
    float4 o  = ((const float4*)g_oc)[(size_t)src * 128 + q];
    float4 tc = ((const float4*)g_tc)[(size_t)b * 128 + q];
    float4 h = make_float4(o.x * tc.x, o.y * tc.y, o.z * tc.z, o.w * tc.w);
    ((float4*)g_h)[(size_t)b * 128 + q] = h;
}

// ---------------- SimpleRNN step: dst = tanh(h@Wr + src@Ur + br) ------------
// Block: 256 thr; tile 64x64, micro 4x4. Ping-pong buffers avoid in-place race.
__global__ void __launch_bounds__(256) k_rnn(
    const float* __restrict__ Wr, const float* __restrict__ Ur,
    const float* __restrict__ br, int parity)
{
    const float* src = parity ? g_hr1 : g_hr0;
    float*       dst = parity ? g_hr0 : g_hr1;
    const int n0 = blockIdx.x * 64;
    const int m0 = blockIdx.y * 64;
    const int l = threadIdx.x;
    const int tx = l & 15, ty = l >> 4;

    __shared__ float As[16][65];
    __shared__ float Bs[16][64];
    float acc[4][4];
#pragma unroll
    for (int i = 0; i < 4; i++)
#pragma unroll
        for (int j = 0; j < 4; j++) acc[i][j] = 0.f;

    const int arow = l >> 2, aq = l & 3;
    const int brow = l >> 4, bn4 = (l & 15) * 4;

    for (int phase = 0; phase < 2; phase++) {
        const float* A = phase ? src : g_h;
        const float* W = phase ? Ur : Wr;
        for (int k0 = 0; k0 < NU; k0 += 16) {
            float4 av = *(const float4*)&A[(size_t)(m0 + arow) * NU + k0 + aq * 4];
            float4 bv = *(const float4*)&W[(size_t)(k0 + brow) * NU + n0 + bn4];
            __syncthreads();
            As[aq * 4 + 0][arow] = av.x;
            As[aq * 4 + 1][arow] = av.y;
            As[aq * 4 + 2][arow] = av.z;
            As[aq * 4 + 3][arow] = av.w;
            *(float4*)&Bs[brow][bn4] = bv;
            __syncthreads();
#pragma unroll
            for (int kk = 0; kk < 16; kk++) {
                float a0 = As[kk][ty * 4 + 0];
                float a1 = As[kk][ty * 4 + 1];
                float a2 = As[kk][ty * 4 + 2];
                float a3 = As[kk][ty * 4 + 3];
                float4 b = *(const float4*)&Bs[kk][tx * 4];
                acc[0][0] = fmaf(a0, b.x, acc[0][0]); acc[0][1] = fmaf(a0, b.y, acc[0][1]);
                acc[0][2] = fmaf(a0, b.z, acc[0][2]); acc[0][3] = fmaf(a0, b.w, acc[0][3]);
                acc[1][0] = fmaf(a1, b.x, acc[1][0]); acc[1][1] = fmaf(a1, b.y, acc[1][1]);
                acc[1][2] = fmaf(a1, b.z, acc[1][2]); acc[1][3] = fmaf(a1, b.w, acc[1][3]);
                acc[2][0] = fmaf(a2, b.x, acc[2][0]); acc[2][1] = fmaf(a2, b.y, acc[2][1]);
                acc[2][2] = fmaf(a2, b.z, acc[2][2]); acc[2][3] = fmaf(a2, b.w, acc[2][3]);
                acc[3][0] = fmaf(a3, b.x, acc[3][0]); acc[3][1] = fmaf(a3, b.y, acc[3][1]);
                acc[3][2] = fmaf(a3, b.z, acc[3][2]); acc[3][3] = fmaf(a3, b.w, acc[3][3]);
            }
        }
    }

#pragma unroll
    for (int i = 0; i < 4; i++) {
        int row = m0 + ty * 4 + i;
#pragma unroll
        for (int j = 0; j < 4; j++) {
            int n = n0 + tx * 4 + j;
            dst[(size_t)row * NU + n] = tanhf(acc[i][j] + br[n]);
        }
    }
}

// ---------------- fold FC: w_eff = w_fc @ w_out, b_eff = b_fc@w_out + b_out -
__global__ void k_weff(const float* __restrict__ wfc, const float* __restrict__ bfc,
                       const float* __restrict__ wout, const float* __restrict__ bout)
{
    int k = threadIdx.x;   // 512
    float s = 0.f;
#pragma unroll 8
    for (int j = 0; j < 32; j++) s += wfc[k * 32 + j] * wout[j];
    g_weff[k] = s;
    if (k == 0) {
        float b = bout[0];
        for (int j = 0; j < 32; j++) b += bfc[j] * wout[j];
        g_beff = b;
    }
}

// ---------------- final projection: one warp per row ------------------------
__global__ void k_out(float* __restrict__ out) {
    int w = (blockIdx.x * blockDim.x + threadIdx.x) >> 5;   // row
    int lane = threadIdx.x & 31;
    const float* h = g_hr1 + (size_t)w * NU;   // T=21: final RNN write lands in hr1
    float s = 0.f;
#pragma unroll
    for (int q = 0; q < 16; q++) {
        int k = lane + q * 32;
        s = fmaf(h[k], g_weff[k], s);
    }
#pragma unroll
    for (int off = 16; off > 0; off >>= 1) s += __shfl_xor_sync(0xffffffffu, s, off);
    if (lane == 0) out[w] = s + g_beff;
}

// ---------------- launcher ---------------------------------------------------
extern "C" void kernel_launch(void* const* d_in, const int* in_sizes, int n_in,
                              void* d_out, int out_size)
{
    const float* x     = (const float*)d_in[0];
    const int*   learn = (const int*)  d_in[1];
    const float* Wk    = (const float*)d_in[2];
    const float* Rk    = (const float*)d_in[3];
    const float* bias  = (const float*)d_in[4];
    const float* Wr    = (const float*)d_in[5];
    const float* Ur    = (const float*)d_in[6];
    const float* br    = (const float*)d_in[7];
    const float* wfc   = (const float*)d_in[8];
    const float* bfc   = (const float*)d_in[9];
    const float* wout  = (const float*)d_in[10];
    const float* bout  = (const float*)d_in[11];
    float* out = (float*)d_out;

    k_init<<<(NB * NU) / 256, 256>>>();
    k_oidx<<<NT, 1024>>>(learn);
    k_weff<<<1, 512>>>(wfc, bfc, wout, bout);

    for (int t = 0; t < NT; t++) {
        k_lstm  <<<dim3(NU / 32, NB / 64), 256>>>(x, Wk, Rk, bias, t);
        k_gather<<<(NB * NU / 4) / 256, 256>>>(t);
        k_rnn   <<<dim3(NU / 64, NB / 64), 256>>>(Wr, Ur, br, t & 1);
    }
    k_out<<<NB / 8, 256>>>(out);
}

// round 2
// speedup vs baseline: 1.2956x; 1.2956x over previous
#include <cuda_runtime.h>
#include <math.h>

#define NB 8192
#define NT 21
#define NF 3
#define NU 512
#define NZ 2048   // 4*U

// B-tile swizzle: insert a 4-word gap every 32 words so float4 column reads
// spread across bank quads. BIDX(c) for c in [0,128) -> [0,140); row len 144.
#define BROW 144
#define BIDX(c) ((c) + (((c) >> 5) << 2))

// ---------------- persistent scratch (device globals) -----------------------
__device__ float g_h  [NB * NU];
__device__ float g_c  [NB * NU];
__device__ float g_hr0[NB * NU];
__device__ float g_hr1[NB * NU];
__device__ float g_oc [NB * NU];
__device__ float g_tc [NB * NU];
__device__ int   g_oidx[NT * NB];
__device__ unsigned char g_m[NT * NB];
__device__ float g_weff[NU];
__device__ float g_beff;

__device__ __forceinline__ float sigf(float z) { return 1.0f / (1.0f + expf(-z)); }

struct SmemGemm {
    float As[16][132];    // [k][row], padded
    float Bs[16][BROW];   // [k][BIDX(col)]
    float ks[3][128];     // input-kernel tile (lstm only)
    float bs[128];        // bias tile (lstm only)
    float xs[128][4];     // x rows (lstm only)
};

// ---------------- init: zero cell state -------------------------------------
__global__ void k_init() {
    int i = blockIdx.x * blockDim.x + threadIdx.x;
    ((float4*)g_c)[i] = make_float4(0.f, 0.f, 0.f, 0.f);
}

// ---------------- mask forcing + cross-batch cummax gather index ------------
__global__ void k_oidx(const int* __restrict__ learn) {
    int t = blockIdx.x;
    int tid = threadIdx.x;
    __shared__ int s_any, s_first;
    __shared__ int s_scan[1024];
    if (tid == 0) { s_any = 0; s_first = 0x7fffffff; }
    __syncthreads();

    int base = tid * 8;
    int m[8]; int la = 0;
#pragma unroll
    for (int j = 0; j < 8; j++) { m[j] = (learn[t * NB + base + j] == 1) ? 1 : 0; la |= m[j]; }
    if (la) atomicOr(&s_any, 1);
    __syncthreads();
    if (tid == 0 && !s_any) m[0] = 1;

    int lf = 0x7fffffff;
#pragma unroll
    for (int j = 0; j < 8; j++) if (m[j] && lf == 0x7fffffff) lf = base + j;
    if (lf != 0x7fffffff) atomicMin(&s_first, lf);

    int run = -1; int lv[8];
#pragma unroll
    for (int j = 0; j < 8; j++) { if (m[j]) run = base + j; lv[j] = run; }
    s_scan[tid] = run;
    __syncthreads();
    for (int off = 1; off < 1024; off <<= 1) {
        int other = (tid >= off) ? s_scan[tid - off] : -1;
        __syncthreads();
        if (other > s_scan[tid]) s_scan[tid] = other;
        __syncthreads();
    }
    int prefix = (tid > 0) ? s_scan[tid - 1] : -1;
    int first = s_first;
#pragma unroll
    for (int j = 0; j < 8; j++) {
        int v = (lv[j] >= 0) ? lv[j] : prefix;
        g_oidx[t * NB + base + j] = (v < 0) ? first : v;
        g_m[t * NB + base + j] = (unsigned char)m[j];
    }
}

// ---------------- LSTM block: 128 rows x (32 u-cols x 4 gates) --------------
__device__ __forceinline__ void lstm_block(
    const float* __restrict__ x, const float* __restrict__ Wk,
    const float* __restrict__ Rk, const float* __restrict__ bias,
    int t, int u0, int m0, int skipH, SmemGemm& S)
{
    const int l  = threadIdx.x;
    const int tx = l & 15, ty = l >> 4;

    float acc[8][4][2];
#pragma unroll
    for (int i = 0; i < 8; i++)
#pragma unroll
        for (int g = 0; g < 4; g++) { acc[i][g][0] = 0.f; acc[i][g][1] = 0.f; }

    // preload x rows, input-kernel tile, bias tile
    for (int idx = l; idx < 384; idx += 256) {
        int r = idx / 3, f = idx - r * 3;
        S.xs[r][f] = x[(size_t)(m0 + r) * (NT * NF) + t * NF + f];
    }
    for (int idx = l; idx < 384; idx += 256) {
        int kk = idx >> 7, cc = idx & 127;
        S.ks[kk][cc] = Wk[kk * NZ + (cc >> 5) * NU + u0 + (cc & 31)];
    }
    if (l < 128) S.bs[l] = bias[(l >> 5) * NU + u0 + (l & 31)];
    __syncthreads();

    if (!skipH) {
        const int arow = l >> 1, aq = l & 1;
        const int bkk = l >> 4, bp = l & 15;
        const float* Asrc = g_h + (size_t)(m0 + arow) * NU + aq * 8;
        const float* Bsrc = Rk + (size_t)bkk * NZ + (bp >> 2) * NU + u0 + (bp & 3) * 8;
        const int bsto = BIDX(bp * 8);

        for (int k0 = 0; k0 < NU; k0 += 16) {
            float4 a0 = *(const float4*)(Asrc + k0);
            float4 a1 = *(const float4*)(Asrc + k0 + 4);
            const float* bptr = Bsrc + (size_t)k0 * NZ;
            float4 b0 = *(const float4*)bptr;
            float4 b1 = *(const float4*)(bptr + 4);
            __syncthreads();
            S.As[aq * 8 + 0][arow] = a0.x;
            S.As[aq * 8 + 1][arow] = a0.y;
            S.As[aq * 8 + 2][arow] = a0.z;
            S.As[aq * 8 + 3][arow] = a0.w;
            S.As[aq * 8 + 4][arow] = a1.x;
            S.As[aq * 8 + 5][arow] = a1.y;
            S.As[aq * 8 + 6][arow] = a1.z;
            S.As[aq * 8 + 7][arow] = a1.w;
            *(float4*)&S.Bs[bkk][bsto]     = b0;
            *(float4*)&S.Bs[bkk][bsto + 4] = b1;
            __syncthreads();
#pragma unroll
            for (int kk = 0; kk < 16; kk++) {
                float4 av0 = *(const float4*)&S.As[kk][ty * 8];
                float4 av1 = *(const float4*)&S.As[kk][ty * 8 + 4];
                float a[8] = {av0.x, av0.y, av0.z, av0.w, av1.x, av1.y, av1.z, av1.w};
                float2 bg[4];
#pragma unroll
                for (int g = 0; g < 4; g++)
                    bg[g] = *(const float2*)&S.Bs[kk][g * 36 + tx * 2]; // BIDX(g*32+tx*2)
#pragma unroll
                for (int i = 0; i < 8; i++)
#pragma unroll
                    for (int g = 0; g < 4; g++) {
                        acc[i][g][0] = fmaf(a[i], bg[g].x, acc[i][g][0]);
                        acc[i][g][1] = fmaf(a[i], bg[g].y, acc[i][g][1]);
                    }
            }
        }
    }

    // x @ kernel contribution (F=3)
#pragma unroll
    for (int f = 0; f < NF; f++) {
        float a[8];
#pragma unroll
        for (int i = 0; i < 8; i++) a[i] = S.xs[ty * 8 + i][f];
        float2 bg[4];
#pragma unroll
        for (int g = 0; g < 4; g++) bg[g] = *(const float2*)&S.ks[f][g * 32 + tx * 2];
#pragma unroll
        for (int i = 0; i < 8; i++)
#pragma unroll
            for (int g = 0; g < 4; g++) {
                acc[i][g][0] = fmaf(a[i], bg[g].x, acc[i][g][0]);
                acc[i][g][1] = fmaf(a[i], bg[g].y, acc[i][g][1]);
            }
    }

    // epilogue: gates, masked c update
#pragma unroll
    for (int i = 0; i < 8; i++) {
        int row = m0 + ty * 8 + i;
        bool mk = g_m[t * NB + row] != 0;
        size_t off = (size_t)row * NU + u0 + tx * 2;
        float2 cold = *(const float2*)&g_c[off];
        float cv[2] = {cold.x, cold.y};
        float2 cnew, tcv, ocv;
        float cn[2], tc[2], oo[2];
#pragma unroll
        for (int j = 0; j < 2; j++) {
            int uu = tx * 2 + j;
            float zi = acc[i][0][j] + S.bs[uu];
            float zf = acc[i][1][j] + S.bs[32 + uu];
            float zg = acc[i][2][j] + S.bs[64 + uu];
            float zo = acc[i][3][j] + S.bs[96 + uu];
            float ig = sigf(zi);
            float fg = sigf(zf);
            float gg = tanhf(zg);
            oo[j] = sigf(zo);
            cn[j] = mk ? fmaf(fg, cv[j], ig * gg) : cv[j];
            tc[j] = tanhf(cn[j]);
        }
        cnew = make_float2(cn[0], cn[1]);
        tcv  = make_float2(tc[0], tc[1]);
        ocv  = make_float2(oo[0], oo[1]);
        *(float2*)&g_c[off]  = cnew;
        *(float2*)&g_tc[off] = tcv;
        *(float2*)&g_oc[off] = ocv;
    }
}

// ---------------- RNN block: 128 rows x 128 cols, 2 K-phases ---------------
__device__ __forceinline__ void rnn_block(
    const float* __restrict__ Wr, const float* __restrict__ Ur,
    const float* __restrict__ br, int parity, int skipU,
    int n0, int m0, SmemGemm& S)
{
    const float* src = parity ? g_hr1 : g_hr0;
    float*       dst = parity ? g_hr0 : g_hr1;
    const int l  = threadIdx.x;
    const int tx = l & 15, ty = l >> 4;

    float acc[8][8];
#pragma unroll
    for (int i = 0; i < 8; i++)
#pragma unroll
        for (int j = 0; j < 8; j++) acc[i][j] = 0.f;

    const int arow = l >> 1, aq = l & 1;
    const int bkk = l >> 4, bp = l & 15;
    const int bsto = BIDX(bp * 8);
    const int nph = skipU ? 1 : 2;

    for (int ph = 0; ph < nph; ph++) {
        const float* A = ph ? src : g_h;
        const float* W = ph ? Ur : Wr;
        const float* Asrc = A + (size_t)(m0 + arow) * NU + aq * 8;
        const float* Bsrc = W + (size_t)bkk * NU + n0 + bp * 8;
        for (int k0 = 0; k0 < NU; k0 += 16) {
            float4 a0 = *(const float4*)(Asrc + k0);
            float4 a1 = *(const float4*)(Asrc + k0 + 4);
            const float* bptr = Bsrc + (size_t)k0 * NU;
            float4 b0 = *(const float4*)bptr;
            float4 b1 = *(const float4*)(bptr + 4);
            __syncthreads();
            S.As[aq * 8 + 0][arow] = a0.x;
            S.As[aq * 8 + 1][arow] = a0.y;
            S.As[aq * 8 + 2][arow] = a0.z;
            S.As[aq * 8 + 3][arow] = a0.w;
            S.As[aq * 8 + 4][arow] = a1.x;
            S.As[aq * 8 + 5][arow] = a1.y;
            S.As[aq * 8 + 6][arow] = a1.z;
            S.As[aq * 8 + 7][arow] = a1.w;
            *(float4*)&S.Bs[bkk][bsto]     = b0;
            *(float4*)&S.Bs[bkk][bsto + 4] = b1;
            __syncthreads();
#pragma unroll
            for (int kk = 0; kk < 16; kk++) {
                float4 av0 = *(const float4*)&S.As[kk][ty * 8];
                float4 av1 = *(const float4*)&S.As[kk][ty * 8 + 4];
                float a[8] = {av0.x, av0.y, av0.z, av0.w, av1.x, av1.y, av1.z, av1.w};
                float4 bv0 = *(const float4*)&S.Bs[kk][BIDX(tx * 8)];
                float4 bv1 = *(const float4*)&S.Bs[kk][BIDX(tx * 8) + 4];
                float b[8] = {bv0.x, bv0.y, bv0.z, bv0.w, bv1.x, bv1.y, bv1.z, bv1.w};
#pragma unroll
                for (int i = 0; i < 8; i++)
#pragma unroll
                    for (int j = 0; j < 8; j++)
                        acc[i][j] = fmaf(a[i], b[j], acc[i][j]);
            }
        }
    }

#pragma unroll
    for (int i = 0; i < 8; i++) {
        int row = m0 + ty * 8 + i;
        float v[8];
#pragma unroll
        for (int j = 0; j < 8; j++) {
            int n = n0 + tx * 8 + j;
            v[j] = tanhf(acc[i][j] + br[n]);
        }
        float4* dp = (float4*)&dst[(size_t)row * NU + n0 + tx * 8];
        dp[0] = make_float4(v[0], v[1], v[2], v[3]);
        dp[1] = make_float4(v[4], v[5], v[6], v[7]);
    }
}

// ---------------- kernels ----------------------------------------------------
__global__ void __launch_bounds__(256, 2) k_lstm0(
    const float* __restrict__ x, const float* __restrict__ Wk,
    const float* __restrict__ Rk, const float* __restrict__ bias)
{
    __shared__ SmemGemm S;
    lstm_block(x, Wk, Rk, bias, 0, (blockIdx.x & 15) * 32, (blockIdx.x >> 4) * 128, 1, S);
}

// fused: lstm for timestep t+1 (blocks 0..1023) + rnn for timestep t (1024..1279)
__global__ void __launch_bounds__(256, 2) k_fused(
    const float* __restrict__ x, const float* __restrict__ Wk,
    const float* __restrict__ Rk, const float* __restrict__ bias,
    const float* __restrict__ Wr, const float* __restrict__ Ur,
    const float* __restrict__ br, int t)
{
    __shared__ SmemGemm S;
    int b = blockIdx.x;
    if (b < 1024) {
        lstm_block(x, Wk, Rk, bias, t + 1, (b & 15) * 32, (b >> 4) * 128, 0, S);
    } else {
        int r = b - 1024;
        rnn_block(Wr, Ur, br, t & 1, t == 0, (r & 3) * 128, (r >> 2) * 128, S);
    }
}

__global__ void __launch_bounds__(256, 2) k_rnn_last(
    const float* __restrict__ Wr, const float* __restrict__ Ur,
    const float* __restrict__ br)
{
    __shared__ SmemGemm S;
    // t=20: parity=0 (src=hr0, dst=hr1)
    rnn_block(Wr, Ur, br, 0, 0, (blockIdx.x & 3) * 128, (blockIdx.x >> 2) * 128, S);
}

// ---------------- cross-batch o gather: h = o_comp[oidx] * tanh(c) ----------
__global__ void k_gather(int t) {
    int i = blockIdx.x * blockDim.x + threadIdx.x;
    int b = i >> 7, q = i & 127;
    int src = g_oidx[t * NB + b];
    float4 o  = ((const float4*)g_oc)[(size_t)src * 128 + q];
    float4 tc = ((const float4*)g_tc)[(size_t)b * 128 + q];
    ((float4*)g_h)[(size_t)b * 128 + q] =
        make_float4(o.x * tc.x, o.y * tc.y, o.z * tc.z, o.w * tc.w);
}

// ---------------- fold FC ----------------------------------------------------
__global__ void k_weff(const float* __restrict__ wfc, const float* __restrict__ bfc,
                       const float* __restrict__ wout, const float* __restrict__ bout)
{
    int k = threadIdx.x;
    float s = 0.f;
#pragma unroll 8
    for (int j = 0; j < 32; j++) s += wfc[k * 32 + j] * wout[j];
    g_weff[k] = s;
    if (k == 0) {
        float b = bout[0];
        for (int j = 0; j < 32; j++) b += bfc[j] * wout[j];
        g_beff = b;
    }
}

// ---------------- final projection ------------------------------------------
__global__ void k_out(float* __restrict__ out) {
    int w = (blockIdx.x * blockDim.x + threadIdx.x) >> 5;
    int lane = threadIdx.x & 31;
    const float* h = g_hr1 + (size_t)w * NU;
    float s = 0.f;
#pragma unroll
    for (int q = 0; q < 16; q++) {
        int k = lane + q * 32;
        s = fmaf(h[k], g_weff[k], s);
    }
#pragma unroll
    for (int off = 16; off > 0; off >>= 1) s += __shfl_xor_sync(0xffffffffu, s, off);
    if (lane == 0) out[w] = s + g_beff;
}

// ---------------- launcher ---------------------------------------------------
extern "C" void kernel_launch(void* const* d_in, const int* in_sizes, int n_in,
                              void* d_out, int out_size)
{
    const float* x     = (const float*)d_in[0];
    const int*   learn = (const int*)  d_in[1];
    const float* Wk    = (const float*)d_in[2];
    const float* Rk    = (const float*)d_in[3];
    const float* bias  = (const float*)d_in[4];
    const float* Wr    = (const float*)d_in[5];
    const float* Ur    = (const float*)d_in[6];
    const float* br    = (const float*)d_in[7];
    const float* wfc   = (const float*)d_in[8];
    const float* bfc   = (const float*)d_in[9];
    const float* wout  = (const float*)d_in[10];
    const float* bout  = (const float*)d_in[11];
    float* out = (float*)d_out;

    k_init<<<(NB * NU / 4) / 256, 256>>>();
    k_oidx<<<NT, 1024>>>(learn);
    k_weff<<<1, 512>>>(wfc, bfc, wout, bout);

    // t = 0 LSTM (h=0 -> recurrent GEMM skipped)
    k_lstm0<<<1024, 256>>>(x, Wk, Rk, bias);
    k_gather<<<(NB * NU / 4) / 256, 256>>>(0);

    for (int t = 0; t < 20; t++) {
        k_fused<<<1280, 256>>>(x, Wk, Rk, bias, Wr, Ur, br, t);
        k_gather<<<(NB * NU / 4) / 256, 256>>>(t + 1);
    }
    k_rnn_last<<<256, 256>>>(Wr, Ur, br);
    k_out<<<NB / 8, 256>>>(out);
}

// round 6
// speedup vs baseline: 2.2413x; 1.7299x over previous
#include <cuda_runtime.h>
#include <cuda_fp16.h>
#include <math.h>
#include <stdint.h>

#define NB 8192
#define NT 21
#define NF 3
#define NU 512
#define NZ 2048

#define KCH 32                    // K per chunk
#define SROW 40                   // smem halves per row (80B, 20 banks -> conflict-free)
#define TILE_B (128 * SROW * 2)   // 10240 B per operand tile
#define STAGE_B (4 * TILE_B)      // Ah/Al/Bh/Bl = 40960 B
#define EPI_OFF (2 * STAGE_B)     // 81920
#define SM_DYN (EPI_OFF + 2048)

// ---------------- persistent scratch --------------------------------------
__device__ float  g_c  [NB * NU];
__device__ float  g_tc [NB * NU];
__device__ float  g_oc [NB * NU];
__device__ float  g_hrf[NB * NU];
__device__ __half g_hah[NB * NU];
__device__ __half g_hal[NB * NU];
__device__ __half g_hph[2][NB * NU];
__device__ __half g_hpl[2][NB * NU];
__device__ __half g_BLh[NZ * NU];      // permuted lstm weights [n=u*4+g][k]
__device__ __half g_BLl[NZ * NU];
__device__ __half g_BRh[NU * 1024];    // rnn concat [n][k: Wr|Ur]
__device__ __half g_BRl[NU * 1024];
__device__ float4 g_Wkp4[NZ];          // (Wk[0][n],Wk[1][n],Wk[2][n],bias[n]) permuted
__device__ int    g_oidx[NT * NB];
__device__ unsigned char g_m[NT * NB];
__device__ float  g_weff[NU];
__device__ float  g_beff;

// ---------------- helpers ---------------------------------------------------
__device__ __forceinline__ uint32_t smem_u32(const void* p) {
    uint32_t a;
    asm("{ .reg .u64 t; cvta.to.shared.u64 t, %1; cvt.u32.u64 %0, t; }" : "=r"(a) : "l"(p));
    return a;
}
__device__ __forceinline__ void cpasync16(uint32_t dst, const void* src) {
    asm volatile("cp.async.ca.shared.global [%0], [%1], 16;" :: "r"(dst), "l"(src));
}
#define CP_COMMIT() asm volatile("cp.async.commit_group;" ::: "memory")
#define CP_WAIT(n)  asm volatile("cp.async.wait_group %0;" :: "n"(n) : "memory")

#define LDSM4(r0, r1, r2, r3, addr) \
    asm volatile("ldmatrix.sync.aligned.m8n8.x4.shared.b16 {%0,%1,%2,%3}, [%4];" \
        : "=r"(r0), "=r"(r1), "=r"(r2), "=r"(r3) : "r"(addr))

__device__ __forceinline__ void mma16816(float* c, const uint32_t* a, uint32_t b0, uint32_t b1) {
    asm volatile(
        "mma.sync.aligned.m16n8k16.row.col.f32.f16.f16.f32 "
        "{%0,%1,%2,%3}, {%4,%5,%6,%7}, {%8,%9}, {%0,%1,%2,%3};"
        : "+f"(c[0]), "+f"(c[1]), "+f"(c[2]), "+f"(c[3])
        : "r"(a[0]), "r"(a[1]), "r"(a[2]), "r"(a[3]), "r"(b0), "r"(b1));
}
__device__ __forceinline__ float sigf(float z) {
    float e = __expf(-z);
    return __fdividef(1.f, 1.f + e);
}
__device__ __forceinline__ float tanhfast(float z) {
    float e = __expf(fminf(2.f * z, 80.f));
    return __fdividef(e - 1.f, e + 1.f);
}
__device__ __forceinline__ void split16(float f, __half& h, __half& l) {
    h = __float2half_rn(f);
    l = __float2half_rn(f - __half2float(h));
}

// ---------------- mask + cummax gather index --------------------------------
__global__ void k_oidx(const int* __restrict__ learn) {
    int t = blockIdx.x;
    int tid = threadIdx.x;
    __shared__ int s_any, s_first;
    __shared__ int s_scan[1024];
    if (tid == 0) { s_any = 0; s_first = 0x7fffffff; }
    __syncthreads();
    int base = tid * 8;
    int m[8]; int la = 0;
#pragma unroll
    for (int j = 0; j < 8; j++) { m[j] = (learn[t * NB + base + j] == 1) ? 1 : 0; la |= m[j]; }
    if (la) atomicOr(&s_any, 1);
    __syncthreads();
    if (tid == 0 && !s_any) m[0] = 1;
    int lf = 0x7fffffff;
#pragma unroll
    for (int j = 0; j < 8; j++) if (m[j] && lf == 0x7fffffff) lf = base + j;
    if (lf != 0x7fffffff) atomicMin(&s_first, lf);
    int run = -1; int lv[8];
#pragma unroll
    for (int j = 0; j < 8; j++) { if (m[j]) run = base + j; lv[j] = run; }
    s_scan[tid] = run;
    __syncthreads();
    for (int off = 1; off < 1024; off <<= 1) {
        int other = (tid >= off) ? s_scan[tid - off] : -1;
        __syncthreads();
        if (other > s_scan[tid]) s_scan[tid] = other;
        __syncthreads();
    }
    int prefix = (tid > 0) ? s_scan[tid - 1] : -1;
    int first = s_first;
#pragma unroll
    for (int j = 0; j < 8; j++) {
        int v = (lv[j] >= 0) ? lv[j] : prefix;
        g_oidx[t * NB + base + j] = (v < 0) ? first : v;
        g_m[t * NB + base + j] = (unsigned char)m[j];
    }
}

// ---------------- weight conversion (once per launch) -----------------------
__global__ void k_convRk(const float* __restrict__ Rk) {
    int idx = blockIdx.x * 256 + threadIdx.x;     // NZ*NU
    int k = idx & 511, n = idx >> 9;
    float v = Rk[(size_t)k * NZ + (n & 3) * NU + (n >> 2)];
    __half h, l; split16(v, h, l);
    g_BLh[idx] = h; g_BLl[idx] = l;
}
__global__ void k_convWU(const float* __restrict__ Wr, const float* __restrict__ Ur) {
    int idx = blockIdx.x * 256 + threadIdx.x;     // NU*1024
    int k = idx & 1023, n = idx >> 10;
    float v = (k < 512) ? Wr[(size_t)k * NU + n] : Ur[(size_t)(k - 512) * NU + n];
    __half h, l; split16(v, h, l);
    g_BRh[idx] = h; g_BRl[idx] = l;
}
__global__ void k_convWkp(const float* __restrict__ Wk, const float* __restrict__ bias) {
    int n = blockIdx.x * 256 + threadIdx.x;       // NZ
    int col = (n & 3) * NU + (n >> 2);
    g_Wkp4[n] = make_float4(Wk[col], Wk[NZ + col], Wk[2 * NZ + col], bias[col]);
}

// ---------------- LSTM t=0 (h=0 -> no GEMM) ---------------------------------
__global__ void k_lstm0s(const float* __restrict__ x) {
    int idx = blockIdx.x * 256 + threadIdx.x;     // NB*NU
    int row = idx >> 9, u = idx & 511;
    float x0 = x[row * (NT * NF) + 0];
    float x1 = x[row * (NT * NF) + 1];
    float x2 = x[row * (NT * NF) + 2];
    float4 w0 = g_Wkp4[u * 4 + 0];
    float4 w2 = g_Wkp4[u * 4 + 2];
    float4 w3 = g_Wkp4[u * 4 + 3];
    float zi = x0 * w0.x + x1 * w0.y + x2 * w0.z + w0.w;
    float zg = x0 * w2.x + x1 * w2.y + x2 * w2.z + w2.w;
    float zo = x0 * w3.x + x1 * w3.y + x2 * w3.z + w3.w;
    bool mk = g_m[row] != 0;
    float c = mk ? sigf(zi) * tanhfast(zg) : 0.f;
    g_c[idx] = c;
    g_tc[idx] = tanhfast(c);
    g_oc[idx] = sigf(zo);
}

// ---------------- gather: h = oc[oidx]*tc -> fp16 hi/lo ---------------------
__global__ void k_gather(int t) {
    int i = blockIdx.x * 256 + threadIdx.x;       // NB*64
    int b = i >> 6, q = i & 63;
    int src = g_oidx[t * NB + b];
    const float4* po = (const float4*)(g_oc + (size_t)src * NU) + q * 2;
    const float4* pt = (const float4*)(g_tc + (size_t)b * NU) + q * 2;
    float4 o0 = po[0], o1 = po[1], t0 = pt[0], t1 = pt[1];
    float h[8] = {o0.x*t0.x, o0.y*t0.y, o0.z*t0.z, o0.w*t0.w,
                  o1.x*t1.x, o1.y*t1.y, o1.z*t1.z, o1.w*t1.w};
    uint32_t hw[4], lw[4];
#pragma unroll
    for (int p = 0; p < 4; p++) {
        __half h0, l0, h1, l1;
        split16(h[p*2], h0, l0); split16(h[p*2+1], h1, l1);
        __half2 hh = __halves2half2(h0, h1);
        __half2 ll = __halves2half2(l0, l1);
        hw[p] = *(uint32_t*)&hh; lw[p] = *(uint32_t*)&ll;
    }
    ((uint4*)g_hah)[i] = make_uint4(hw[0], hw[1], hw[2], hw[3]);
    ((uint4*)g_hal)[i] = make_uint4(lw[0], lw[1], lw[2], lw[3]);
}

// ---------------- fused HMMA GEMM kernel ------------------------------------
// blocks [0, nLstm): LSTM step tL (D[8192 x 2048-permuted], tiles 128x128)
// blocks [nLstm,..): RNN step tR (D[8192 x 512], K=1024 concat, or 512 @ tR=0)
__global__ void __launch_bounds__(256, 2) k_hmma(
    const float* __restrict__ x, const float* __restrict__ br,
    int tL, int tR, int nLstm, int par)
{
    extern __shared__ char smraw[];
    const uint32_t sb = smem_u32(smraw);
    const int tid = threadIdx.x;
    const int w = tid >> 5, lane = tid & 31;
    const int wm = w & 3, wn = w >> 2;

    const bool isL = (int)blockIdx.x < nLstm;
    int m0, n0, nch, t, ldb;
    const __half *Bh, *Bl;
    const __half *A2h = nullptr, *A2l = nullptr;
    if (isL) {
        n0 = (blockIdx.x & 15) * 128; m0 = ((int)blockIdx.x >> 4) * 128;
        nch = 16; t = tL; Bh = g_BLh; Bl = g_BLl; ldb = 512;
    } else {
        int r = blockIdx.x - nLstm;
        n0 = (r & 3) * 128; m0 = (r >> 2) * 128;
        nch = (tR == 0) ? 16 : 32; t = tR; Bh = g_BRh; Bl = g_BRl; ldb = 1024;
        A2h = g_hph[par]; A2l = g_hpl[par];
    }

    float4* sWkp = (float4*)(smraw + EPI_OFF);
    float*  sbr  = (float*)(smraw + EPI_OFF);
    if (isL) { if (tid < 128) sWkp[tid] = g_Wkp4[n0 + tid]; }
    else     { if (tid < 128) sbr[tid]  = br[n0 + tid]; }

    float acc[2][8][4];
#pragma unroll
    for (int i = 0; i < 2; i++)
#pragma unroll
        for (int j = 0; j < 8; j++)
#pragma unroll
            for (int q = 0; q < 4; q++) acc[i][j][q] = 0.f;

    auto load_chunk = [&](int c, int s) {
        const __half *Ah, *Al; int kc;
        if (isL || c < 16) { Ah = g_hah; Al = g_hal; kc = c * KCH; }
        else               { Ah = A2h;   Al = A2l;   kc = (c - 16) * KCH; }
        const int kb = c * KCH;
        const uint32_t st = sb + s * STAGE_B;
#pragma unroll
        for (int q = 0; q < 2; q++) {
            int i = tid + q * 256;
            int row = i >> 2, seg = i & 3;
            uint32_t so = row * (SROW * 2) + seg * 16;
            cpasync16(st +              so, Ah + (size_t)(m0 + row) * 512 + kc + seg * 8);
            cpasync16(st +     TILE_B + so, Al + (size_t)(m0 + row) * 512 + kc + seg * 8);
            cpasync16(st + 2 * TILE_B + so, Bh + (size_t)(n0 + row) * ldb + kb + seg * 8);
            cpasync16(st + 3 * TILE_B + so, Bl + (size_t)(n0 + row) * ldb + kb + seg * 8);
        }
    };

    const uint32_t arow = (lane & 15) * (SROW * 2) + ((lane >> 4) << 4);

    auto compute_chunk = [&](int s) {
        const uint32_t st = sb + s * STAGE_B;
#pragma unroll
        for (int ks = 0; ks < 2; ks++) {
            const uint32_t ko = ks * 32;             // 16 halves
            uint32_t ah[2][4], al[2][4];
#pragma unroll
            for (int mt = 0; mt < 2; mt++) {
                uint32_t aoff = (wm * 32 + mt * 16) * (SROW * 2) + arow + ko;
                LDSM4(ah[mt][0], ah[mt][1], ah[mt][2], ah[mt][3], st + aoff);
                LDSM4(al[mt][0], al[mt][1], al[mt][2], al[mt][3], st + TILE_B + aoff);
            }
#pragma unroll
            for (int np = 0; np < 4; np++) {
                uint32_t bo = (wn * 64 + np * 16) * (SROW * 2) + arow + ko;
                uint32_t bh[4], bl[4];
                LDSM4(bh[0], bh[1], bh[2], bh[3], st + 2 * TILE_B + bo);
                LDSM4(bl[0], bl[1], bl[2], bl[3], st + 3 * TILE_B + bo);
#pragma unroll
                for (int mt = 0; mt < 2; mt++) {
                    float* ce = acc[mt][np * 2];
                    float* co = acc[mt][np * 2 + 1];
                    mma16816(ce, ah[mt], bh[0], bh[2]);
                    mma16816(ce, ah[mt], bl[0], bl[2]);
                    mma16816(ce, al[mt], bh[0], bh[2]);
                    mma16816(co, ah[mt], bh[1], bh[3]);
                    mma16816(co, ah[mt], bl[1], bl[3]);
                    mma16816(co, al[mt], bh[1], bh[3]);
                }
            }
        }
    };

    load_chunk(0, 0); CP_COMMIT();
    for (int c = 0; c < nch; c++) {
        if (c + 1 < nch) { load_chunk(c + 1, (c + 1) & 1); CP_COMMIT(); CP_WAIT(1); }
        else             { CP_WAIT(0); }
        __syncthreads();
        compute_chunk(c & 1);
        __syncthreads();
    }

    // ---- epilogue ----
    const int grow = lane >> 2, tig = lane & 3;
    const bool evn = (tig & 1) == 0;

    if (isL) {
        float xs[2][3]; bool mk[2]; int rows[2];
#pragma unroll
        for (int mt = 0; mt < 2; mt++) {
            rows[mt] = m0 + wm * 32 + mt * 16 + grow + (evn ? 0 : 8);
            const float* xp = x + rows[mt] * (NT * NF) + t * NF;
            xs[mt][0] = xp[0]; xs[mt][1] = xp[1]; xs[mt][2] = xp[2];
            mk[mt] = g_m[t * NB + rows[mt]] != 0;
        }
#pragma unroll
        for (int mt = 0; mt < 2; mt++) {
#pragma unroll
            for (int nt = 0; nt < 8; nt++) {
                float* c = acc[mt][nt];
                float p0 = __shfl_xor_sync(0xffffffffu, c[0], 1);
                float p1 = __shfl_xor_sync(0xffffffffu, c[1], 1);
                float p2 = __shfl_xor_sync(0xffffffffu, c[2], 1);
                float p3 = __shfl_xor_sync(0xffffffffu, c[3], 1);
                float zi, zf, zg, zo;
                if (evn) { zi = c[0]; zf = c[1]; zg = p0; zo = p1; }
                else     { zi = p2; zf = p3; zg = c[2]; zo = c[3]; }
                int u_loc = wn * 16 + nt * 2 + (tig >> 1);
                float4 w0 = sWkp[u_loc * 4 + 0];
                float4 w1 = sWkp[u_loc * 4 + 1];
                float4 w2 = sWkp[u_loc * 4 + 2];
                float4 w3 = sWkp[u_loc * 4 + 3];
                zi += xs[mt][0]*w0.x + xs[mt][1]*w0.y + xs[mt][2]*w0.z + w0.w;
                zf += xs[mt][0]*w1.x + xs[mt][1]*w1.y + xs[mt][2]*w1.z + w1.w;
                zg += xs[mt][0]*w2.x + xs[mt][1]*w2.y + xs[mt][2]*w2.z + w2.w;
                zo += xs[mt][0]*w3.x + xs[mt][1]*w3.y + xs[mt][2]*w3.z + w3.w;
                int u = (n0 >> 2) + u_loc;
                size_t off = (size_t)rows[mt] * NU + u;
                float ig = sigf(zi), fg = sigf(zf), gg = tanhfast(zg), og = sigf(zo);
                float cold = g_c[off];
                float cn = mk[mt] ? fmaf(fg, cold, ig * gg) : cold;
                g_c[off]  = cn;
                g_tc[off] = tanhfast(cn);
                g_oc[off] = og;
            }
        }
    } else {
        __half* dh = g_hph[par ^ 1];
        __half* dl = g_hpl[par ^ 1];
#pragma unroll
        for (int mt = 0; mt < 2; mt++) {
            int r0 = m0 + wm * 32 + mt * 16 + grow;
#pragma unroll
            for (int nt = 0; nt < 8; nt++) {
                float* c = acc[mt][nt];
                int ncl = wn * 64 + nt * 8 + tig * 2;
                int nc = n0 + ncl;
                float b0 = sbr[ncl], b1 = sbr[ncl + 1];
                float v00 = tanhfast(c[0] + b0), v01 = tanhfast(c[1] + b1);
                float v10 = tanhfast(c[2] + b0), v11 = tanhfast(c[3] + b1);
                *(float2*)&g_hrf[(size_t)r0 * NU + nc]       = make_float2(v00, v01);
                *(float2*)&g_hrf[(size_t)(r0 + 8) * NU + nc] = make_float2(v10, v11);
                __half h0, l0, h1, l1;
                split16(v00, h0, l0); split16(v01, h1, l1);
                *(__half2*)&dh[(size_t)r0 * NU + nc] = __halves2half2(h0, h1);
                *(__half2*)&dl[(size_t)r0 * NU + nc] = __halves2half2(l0, l1);
                split16(v10, h0, l0); split16(v11, h1, l1);
                *(__half2*)&dh[(size_t)(r0 + 8) * NU + nc] = __halves2half2(h0, h1);
                *(__half2*)&dl[(size_t)(r0 + 8) * NU + nc] = __halves2half2(l0, l1);
            }
        }
    }
}

// ---------------- fold FC + final projection --------------------------------
__global__ void k_weff(const float* __restrict__ wfc, const float* __restrict__ bfc,
                       const float* __restrict__ wout, const float* __restrict__ bout)
{
    int k = threadIdx.x;
    float s = 0.f;
#pragma unroll 8
    for (int j = 0; j < 32; j++) s += wfc[k * 32 + j] * wout[j];
    g_weff[k] = s;
    if (k == 0) {
        float b = bout[0];
        for (int j = 0; j < 32; j++) b += bfc[j] * wout[j];
        g_beff = b;
    }
}
__global__ void k_out(float* __restrict__ out) {
    int w = (blockIdx.x * blockDim.x + threadIdx.x) >> 5;
    int lane = threadIdx.x & 31;
    const float* h = g_hrf + (size_t)w * NU;
    float s = 0.f;
#pragma unroll
    for (int q = 0; q < 16; q++) s = fmaf(h[lane + q * 32], g_weff[lane + q * 32], s);
#pragma unroll
    for (int off = 16; off > 0; off >>= 1) s += __shfl_xor_sync(0xffffffffu, s, off);
    if (lane == 0) out[w] = s + g_beff;
}

// ---------------- launcher ---------------------------------------------------
extern "C" void kernel_launch(void* const* d_in, const int* in_sizes, int n_in,
                              void* d_out, int out_size)
{
    const float* x     = (const float*)d_in[0];
    const int*   learn = (const int*)  d_in[1];
    const float* Wk    = (const float*)d_in[2];
    const float* Rk    = (const float*)d_in[3];
    const float* bias  = (const float*)d_in[4];
    const float* Wr    = (const float*)d_in[5];
    const float* Ur    = (const float*)d_in[6];
    const float* br    = (const float*)d_in[7];
    const float* wfc   = (const float*)d_in[8];
    const float* bfc   = (const float*)d_in[9];
    const float* wout  = (const float*)d_in[10];
    const float* bout  = (const float*)d_in[11];
    float* out = (float*)d_out;

    cudaFuncSetAttribute(k_hmma, cudaFuncAttributeMaxDynamicSharedMemorySize, SM_DYN);

    k_oidx<<<NT, 1024>>>(learn);
    k_weff<<<1, 512>>>(wfc, bfc, wout, bout);
    k_convRk<<<(NZ * NU) / 256, 256>>>(Rk);
    k_convWU<<<(NU * 1024) / 256, 256>>>(Wr, Ur);
    k_convWkp<<<NZ / 256, 256>>>(Wk, bias);

    k_lstm0s<<<(NB * NU) / 256, 256>>>(x);
    k_gather<<<(NB * 64) / 256, 256>>>(0);

    for (int t = 0; t < 20; t++) {
        // lstm step t+1 (1024 tiles) + rnn step t (256 tiles)
        k_hmma<<<1280, 256, SM_DYN>>>(x, br, t + 1, t, 1024, t & 1);
        k_gather<<<(NB * 64) / 256, 256>>>(t + 1);
    }
    // final rnn step t=20
    k_hmma<<<256, 256, SM_DYN>>>(x, br, -1, 20, 0, 0);
    k_out<<<NB / 8, 256>>>(out);
}

// round 8
// speedup vs baseline: 2.8016x; 1.2500x over previous
#include <cuda_runtime.h>
#include <cuda_fp16.h>
#include <math.h>
#include <stdint.h>

#define NB 8192
#define NT 21
#define NF 3
#define NU 512
#define NZ 2048

#define KCH 32                    // K per chunk
#define SROW 40                   // smem halves per row (80B, 20 banks -> conflict-free)
#define TILE_B (128 * SROW * 2)   // 10240 B per operand tile
#define STAGE_B (3 * TILE_B)      // Ah/Bh/Bl = 30720 B
#define EPI_OFF (2 * STAGE_B)     // 61440
#define SM_DYN (EPI_OFF + 2048)

// ---------------- persistent scratch --------------------------------------
__device__ float  g_c  [NB * NU];
__device__ float  g_tc [NB * NU];
__device__ float  g_oc [NB * NU];
__device__ float  g_hrf[NB * NU];
__device__ __half g_hah[NB * NU];      // LSTM h (fp16, A operand)
__device__ __half g_hph[2][NB * NU];   // RNN state ping-pong (fp16)
__device__ __half g_BLh[NZ * NU];      // permuted lstm weights [n=u*4+g][k], hi
__device__ __half g_BLl[NZ * NU];      // lo
__device__ __half g_BRh[NU * 1024];    // rnn concat [n][k: Wr|Ur], hi
__device__ __half g_BRl[NU * 1024];    // lo
__device__ float4 g_Wkp4[NZ];          // (Wk[0][n],Wk[1][n],Wk[2][n],bias[n]) permuted
__device__ int    g_oidx[NT * NB];
__device__ unsigned char g_m[NT * NB];
__device__ float  g_weff[NU];
__device__ float  g_beff;

// ---------------- helpers ---------------------------------------------------
__device__ __forceinline__ uint32_t smem_u32(const void* p) {
    uint32_t a;
    asm("{ .reg .u64 t; cvta.to.shared.u64 t, %1; cvt.u32.u64 %0, t; }" : "=r"(a) : "l"(p));
    return a;
}
__device__ __forceinline__ void cpasync16(uint32_t dst, const void* src) {
    asm volatile("cp.async.ca.shared.global [%0], [%1], 16;" :: "r"(dst), "l"(src));
}
#define CP_COMMIT() asm volatile("cp.async.commit_group;" ::: "memory")
#define CP_WAIT(n)  asm volatile("cp.async.wait_group %0;" :: "n"(n) : "memory")

#define LDSM4(r0, r1, r2, r3, addr) \
    asm volatile("ldmatrix.sync.aligned.m8n8.x4.shared.b16 {%0,%1,%2,%3}, [%4];" \
        : "=r"(r0), "=r"(r1), "=r"(r2), "=r"(r3) : "r"(addr))

__device__ __forceinline__ void mma16816(float* c, const uint32_t* a, uint32_t b0, uint32_t b1) {
    asm volatile(
        "mma.sync.aligned.m16n8k16.row.col.f32.f16.f16.f32 "
        "{%0,%1,%2,%3}, {%4,%5,%6,%7}, {%8,%9}, {%0,%1,%2,%3};"
        : "+f"(c[0]), "+f"(c[1]), "+f"(c[2]), "+f"(c[3])
        : "r"(a[0]), "r"(a[1]), "r"(a[2]), "r"(a[3]), "r"(b0), "r"(b1));
}
__device__ __forceinline__ float sigf(float z) {
    float e = __expf(-z);
    return __fdividef(1.f, 1.f + e);
}
__device__ __forceinline__ float tanhfast(float z) {
    float e = __expf(fminf(2.f * z, 80.f));
    return __fdividef(e - 1.f, e + 1.f);
}
__device__ __forceinline__ void split16(float f, __half& h, __half& l) {
    h = __float2half_rn(f);
    l = __float2half_rn(f - __half2float(h));
}

// ---------------- mask + cummax gather index --------------------------------
__global__ void k_oidx(const int* __restrict__ learn) {
    int t = blockIdx.x;
    int tid = threadIdx.x;
    __shared__ int s_any, s_first;
    __shared__ int s_scan[1024];
    if (tid == 0) { s_any = 0; s_first = 0x7fffffff; }
    __syncthreads();
    int base = tid * 8;
    int m[8]; int la = 0;
#pragma unroll
    for (int j = 0; j < 8; j++) { m[j] = (learn[t * NB + base + j] == 1) ? 1 : 0; la |= m[j]; }
    if (la) atomicOr(&s_any, 1);
    __syncthreads();
    if (tid == 0 && !s_any) m[0] = 1;
    int lf = 0x7fffffff;
#pragma unroll
    for (int j = 0; j < 8; j++) if (m[j] && lf == 0x7fffffff) lf = base + j;
    if (lf != 0x7fffffff) atomicMin(&s_first, lf);
    int run = -1; int lv[8];
#pragma unroll
    for (int j = 0; j < 8; j++) { if (m[j]) run = base + j; lv[j] = run; }
    s_scan[tid] = run;
    __syncthreads();
    for (int off = 1; off < 1024; off <<= 1) {
        int other = (tid >= off) ? s_scan[tid - off] : -1;
        __syncthreads();
        if (other > s_scan[tid]) s_scan[tid] = other;
        __syncthreads();
    }
    int prefix = (tid > 0) ? s_scan[tid - 1] : -1;
    int first = s_first;
#pragma unroll
    for (int j = 0; j < 8; j++) {
        int v = (lv[j] >= 0) ? lv[j] : prefix;
        g_oidx[t * NB + base + j] = (v < 0) ? first : v;
        g_m[t * NB + base + j] = (unsigned char)m[j];
    }
}

// ---------------- weight conversion (once per launch) -----------------------
__global__ void k_convRk(const float* __restrict__ Rk) {
    int idx = blockIdx.x * 256 + threadIdx.x;     // NZ*NU
    int k = idx & 511, n = idx >> 9;
    float v = Rk[(size_t)k * NZ + (n & 3) * NU + (n >> 2)];
    __half h, l; split16(v, h, l);
    g_BLh[idx] = h; g_BLl[idx] = l;
}
__global__ void k_convWU(const float* __restrict__ Wr, const float* __restrict__ Ur) {
    int idx = blockIdx.x * 256 + threadIdx.x;     // NU*1024
    int k = idx & 1023, n = idx >> 10;
    float v = (k < 512) ? Wr[(size_t)k * NU + n] : Ur[(size_t)(k - 512) * NU + n];
    __half h, l; split16(v, h, l);
    g_BRh[idx] = h; g_BRl[idx] = l;
}
__global__ void k_convWkp(const float* __restrict__ Wk, const float* __restrict__ bias) {
    int n = blockIdx.x * 256 + threadIdx.x;       // NZ
    int col = (n & 3) * NU + (n >> 2);
    g_Wkp4[n] = make_float4(Wk[col], Wk[NZ + col], Wk[2 * NZ + col], bias[col]);
}

// ---------------- LSTM t=0 (h=0 -> no GEMM) ---------------------------------
__global__ void k_lstm0s(const float* __restrict__ x) {
    int idx = blockIdx.x * 256 + threadIdx.x;     // NB*NU
    int row = idx >> 9, u = idx & 511;
    float x0 = x[row * (NT * NF) + 0];
    float x1 = x[row * (NT * NF) + 1];
    float x2 = x[row * (NT * NF) + 2];
    float4 w0 = g_Wkp4[u * 4 + 0];
    float4 w2 = g_Wkp4[u * 4 + 2];
    float4 w3 = g_Wkp4[u * 4 + 3];
    float zi = x0 * w0.x + x1 * w0.y + x2 * w0.z + w0.w;
    float zg = x0 * w2.x + x1 * w2.y + x2 * w2.z + w2.w;
    float zo = x0 * w3.x + x1 * w3.y + x2 * w3.z + w3.w;
    bool mk = g_m[row] != 0;
    float c = mk ? sigf(zi) * tanhfast(zg) : 0.f;
    g_c[idx] = c;
    g_tc[idx] = tanhfast(c);
    g_oc[idx] = sigf(zo);
}

// ---------------- gather: h = oc[oidx]*tc -> fp16 ---------------------------
__global__ void k_gather(int t) {
    int i = blockIdx.x * 256 + threadIdx.x;       // NB*64
    int b = i >> 6, q = i & 63;
    int src = g_oidx[t * NB + b];
    const float4* po = (const float4*)(g_oc + (size_t)src * NU) + q * 2;
    const float4* pt = (const float4*)(g_tc + (size_t)b * NU) + q * 2;
    float4 o0 = po[0], o1 = po[1], t0 = pt[0], t1 = pt[1];
    __half2 h0 = __floats2half2_rn(o0.x * t0.x, o0.y * t0.y);
    __half2 h1 = __floats2half2_rn(o0.z * t0.z, o0.w * t0.w);
    __half2 h2 = __floats2half2_rn(o1.x * t1.x, o1.y * t1.y);
    __half2 h3 = __floats2half2_rn(o1.z * t1.z, o1.w * t1.w);
    ((uint4*)g_hah)[i] = make_uint4(*(uint32_t*)&h0, *(uint32_t*)&h1,
                                    *(uint32_t*)&h2, *(uint32_t*)&h3);
}

// ---------------- fused HMMA GEMM kernel ------------------------------------
// blocks [0, nLstm): LSTM step tL (D[8192 x 2048-permuted], tiles 128x128)
// blocks [nLstm,..): RNN step tR (D[8192 x 512], K=1024 concat, or 512 @ tR=0)
__global__ void __launch_bounds__(256, 2) k_hmma(
    const float* __restrict__ x, const float* __restrict__ br,
    int tL, int tR, int nLstm, int par)
{
    extern __shared__ char smraw[];
    const uint32_t sb = smem_u32(smraw);
    const int tid = threadIdx.x;
    const int w = tid >> 5, lane = tid & 31;
    const int wm = w & 3, wn = w >> 2;

    const bool isL = (int)blockIdx.x < nLstm;
    int m0, n0, nch, t, ldb;
    const __half *Bh, *Bl;
    const __half *A2h = nullptr;
    if (isL) {
        n0 = (blockIdx.x & 15) * 128; m0 = ((int)blockIdx.x >> 4) * 128;
        nch = 16; t = tL; Bh = g_BLh; Bl = g_BLl; ldb = 512;
    } else {
        int r = blockIdx.x - nLstm;
        n0 = (r & 3) * 128; m0 = (r >> 2) * 128;
        nch = (tR == 0) ? 16 : 32; t = tR; Bh = g_BRh; Bl = g_BRl; ldb = 1024;
        A2h = g_hph[par];
    }

    float4* sWkp = (float4*)(smraw + EPI_OFF);
    float*  sbr  = (float*)(smraw + EPI_OFF);
    if (isL) { if (tid < 128) sWkp[tid] = g_Wkp4[n0 + tid]; }
    else     { if (tid < 128) sbr[tid]  = br[n0 + tid]; }

    float acc[2][8][4];
#pragma unroll
    for (int i = 0; i < 2; i++)
#pragma unroll
        for (int j = 0; j < 8; j++)
#pragma unroll
            for (int q = 0; q < 4; q++) acc[i][j][q] = 0.f;

    auto load_chunk = [&](int c, int s) {
        const __half* Ah; int kc;
        if (isL || c < 16) { Ah = g_hah; kc = c * KCH; }
        else               { Ah = A2h;   kc = (c - 16) * KCH; }
        const int kb = c * KCH;
        const uint32_t st = sb + s * STAGE_B;
#pragma unroll
        for (int q = 0; q < 2; q++) {
            int i = tid + q * 256;
            int row = i >> 2, seg = i & 3;
            uint32_t so = row * (SROW * 2) + seg * 16;
            cpasync16(st +              so, Ah + (size_t)(m0 + row) * 512 + kc + seg * 8);
            cpasync16(st +     TILE_B + so, Bh + (size_t)(n0 + row) * ldb + kb + seg * 8);
            cpasync16(st + 2 * TILE_B + so, Bl + (size_t)(n0 + row) * ldb + kb + seg * 8);
        }
    };

    const uint32_t arow = (lane & 15) * (SROW * 2) + ((lane >> 4) << 4);

    auto compute_chunk = [&](int s) {
        const uint32_t st = sb + s * STAGE_B;
#pragma unroll
        for (int ks = 0; ks < 2; ks++) {
            const uint32_t ko = ks * 32;             // 16 halves
            uint32_t ah[2][4];
#pragma unroll
            for (int mt = 0; mt < 2; mt++) {
                uint32_t aoff = (wm * 32 + mt * 16) * (SROW * 2) + arow + ko;
                LDSM4(ah[mt][0], ah[mt][1], ah[mt][2], ah[mt][3], st + aoff);
            }
#pragma unroll
            for (int np = 0; np < 4; np++) {
                uint32_t bo = (wn * 64 + np * 16) * (SROW * 2) + arow + ko;
                uint32_t bh[4], bl[4];
                LDSM4(bh[0], bh[1], bh[2], bh[3], st +     TILE_B + bo);
                LDSM4(bl[0], bl[1], bl[2], bl[3], st + 2 * TILE_B + bo);
#pragma unroll
                for (int mt = 0; mt < 2; mt++) {
                    float* ce = acc[mt][np * 2];
                    float* co = acc[mt][np * 2 + 1];
                    mma16816(ce, ah[mt], bh[0], bh[2]);
                    mma16816(ce, ah[mt], bl[0], bl[2]);
                    mma16816(co, ah[mt], bh[1], bh[3]);
                    mma16816(co, ah[mt], bl[1], bl[3]);
                }
            }
        }
    };

    load_chunk(0, 0); CP_COMMIT();
    for (int c = 0; c < nch; c++) {
        if (c + 1 < nch) { load_chunk(c + 1, (c + 1) & 1); CP_COMMIT(); CP_WAIT(1); }
        else             { CP_WAIT(0); }
        __syncthreads();
        compute_chunk(c & 1);
        __syncthreads();
    }

    // ---- epilogue ----
    const int grow = lane >> 2, tig = lane & 3;
    const bool evn = (tig & 1) == 0;

    if (isL) {
        float xs[2][3]; bool mk[2]; int rows[2];
#pragma unroll
        for (int mt = 0; mt < 2; mt++) {
            rows[mt] = m0 + wm * 32 + mt * 16 + grow + (evn ? 0 : 8);
            const float* xp = x + rows[mt] * (NT * NF) + t * NF;
            xs[mt][0] = xp[0]; xs[mt][1] = xp[1]; xs[mt][2] = xp[2];
            mk[mt] = g_m[t * NB + rows[mt]] != 0;
        }
#pragma unroll
        for (int mt = 0; mt < 2; mt++) {
#pragma unroll
            for (int nt = 0; nt < 8; nt++) {
                float* c = acc[mt][nt];
                float p0 = __shfl_xor_sync(0xffffffffu, c[0], 1);
                float p1 = __shfl_xor_sync(0xffffffffu, c[1], 1);
                float p2 = __shfl_xor_sync(0xffffffffu, c[2], 1);
                float p3 = __shfl_xor_sync(0xffffffffu, c[3], 1);
                float zi, zf, zg, zo;
                if (evn) { zi = c[0]; zf = c[1]; zg = p0; zo = p1; }
                else     { zi = p2; zf = p3; zg = c[2]; zo = c[3]; }
                int u_loc = wn * 16 + nt * 2 + (tig >> 1);
                float4 w0 = sWkp[u_loc * 4 + 0];
                float4 w1 = sWkp[u_loc * 4 + 1];
                float4 w2 = sWkp[u_loc * 4 + 2];
                float4 w3 = sWkp[u_loc * 4 + 3];
                zi += xs[mt][0]*w0.x + xs[mt][1]*w0.y + xs[mt][2]*w0.z + w0.w;
                zf += xs[mt][0]*w1.x + xs[mt][1]*w1.y + xs[mt][2]*w1.z + w1.w;
                zg += xs[mt][0]*w2.x + xs[mt][1]*w2.y + xs[mt][2]*w2.z + w2.w;
                zo += xs[mt][0]*w3.x + xs[mt][1]*w3.y + xs[mt][2]*w3.z + w3.w;
                int u = (n0 >> 2) + u_loc;
                size_t off = (size_t)rows[mt] * NU + u;
                float ig = sigf(zi), fg = sigf(zf), gg = tanhfast(zg), og = sigf(zo);
                float cold = g_c[off];
                float cn = mk[mt] ? fmaf(fg, cold, ig * gg) : cold;
                g_c[off]  = cn;
                g_tc[off] = tanhfast(cn);
                g_oc[off] = og;
            }
        }
    } else {
        __half* dh = g_hph[par ^ 1];
#pragma unroll
        for (int mt = 0; mt < 2; mt++) {
            int r0 = m0 + wm * 32 + mt * 16 + grow;
#pragma unroll
            for (int nt = 0; nt < 8; nt++) {
                float* c = acc[mt][nt];
                int ncl = wn * 64 + nt * 8 + tig * 2;
                int nc = n0 + ncl;
                float b0 = sbr[ncl], b1 = sbr[ncl + 1];
                float v00 = tanhfast(c[0] + b0), v01 = tanhfast(c[1] + b1);
                float v10 = tanhfast(c[2] + b0), v11 = tanhfast(c[3] + b1);
                *(float2*)&g_hrf[(size_t)r0 * NU + nc]       = make_float2(v00, v01);
                *(float2*)&g_hrf[(size_t)(r0 + 8) * NU + nc] = make_float2(v10, v11);
                __half2 d0 = __floats2half2_rn(v00, v01);
                __half2 d1 = __floats2half2_rn(v10, v11);
                *(__half2*)&dh[(size_t)r0 * NU + nc]       = d0;
                *(__half2*)&dh[(size_t)(r0 + 8) * NU + nc] = d1;
            }
        }
    }
}

// ---------------- fold FC + final projection --------------------------------
__global__ void k_weff(const float* __restrict__ wfc, const float* __restrict__ bfc,
                       const float* __restrict__ wout, const float* __restrict__ bout)
{
    int k = threadIdx.x;
    float s = 0.f;
#pragma unroll 8
    for (int j = 0; j < 32; j++) s += wfc[k * 32 + j] * wout[j];
    g_weff[k] = s;
    if (k == 0) {
        float b = bout[0];
        for (int j = 0; j < 32; j++) b += bfc[j] * wout[j];
        g_beff = b;
    }
}
__global__ void k_out(float* __restrict__ out) {
    int w = (blockIdx.x * blockDim.x + threadIdx.x) >> 5;
    int lane = threadIdx.x & 31;
    const float* h = g_hrf + (size_t)w * NU;
    float s = 0.f;
#pragma unroll
    for (int q = 0; q < 16; q++) s = fmaf(h[lane + q * 32], g_weff[lane + q * 32], s);
#pragma unroll
    for (int off = 16; off > 0; off >>= 1) s += __shfl_xor_sync(0xffffffffu, s, off);
    if (lane == 0) out[w] = s + g_beff;
}

// ---------------- launcher ---------------------------------------------------
extern "C" void kernel_launch(void* const* d_in, const int* in_sizes, int n_in,
                              void* d_out, int out_size)
{
    const float* x     = (const float*)d_in[0];
    const int*   learn = (const int*)  d_in[1];
    const float* Wk    = (const float*)d_in[2];
    const float* Rk    = (const float*)d_in[3];
    const float* bias  = (const float*)d_in[4];
    const float* Wr    = (const float*)d_in[5];
    const float* Ur    = (const float*)d_in[6];
    const float* br    = (const float*)d_in[7];
    const float* wfc   = (const float*)d_in[8];
    const float* bfc   = (const float*)d_in[9];
    const float* wout  = (const float*)d_in[10];
    const float* bout  = (const float*)d_in[11];
    float* out = (float*)d_out;

    cudaFuncSetAttribute(k_hmma, cudaFuncAttributeMaxDynamicSharedMemorySize, SM_DYN);

    k_oidx<<<NT, 1024>>>(learn);
    k_weff<<<1, 512>>>(wfc, bfc, wout, bout);
    k_convRk<<<(NZ * NU) / 256, 256>>>(Rk);
    k_convWU<<<(NU * 1024) / 256, 256>>>(Wr, Ur);
    k_convWkp<<<NZ / 256, 256>>>(Wk, bias);

    k_lstm0s<<<(NB * NU) / 256, 256>>>(x);
    k_gather<<<(NB * 64) / 256, 256>>>(0);

    for (int t = 0; t < 20; t++) {
        // lstm step t+1 (1024 tiles) + rnn step t (256 tiles)
        k_hmma<<<1280, 256, SM_DYN>>>(x, br, t + 1, t, 1024, t & 1);
        k_gather<<<(NB * 64) / 256, 256>>>(t + 1);
    }
    // final rnn step t=20
    k_hmma<<<256, 256, SM_DYN>>>(x, br, -1, 20, 0, 0);
    k_out<<<NB / 8, 256>>>(out);
}